// round 1
// baseline (speedup 1.0000x reference)
#include <cuda_runtime.h>
#include <math.h>

#define BB 128
#define QQ 500
#define NCLS 80
#define TT 64
#define NTHREADS 512
#define TPAD 65   // padded row stride in smem: conflict-free column scans

// map float -> order-preserving unsigned (ascending)
__device__ __forceinline__ unsigned int f2ord(float f) {
    unsigned int u = __float_as_uint(f);
    return (u & 0x80000000u) ? ~u : (u | 0x80000000u);
}

__global__ __launch_bounds__(NTHREADS, 1)
void hungarian_lite_kernel(const float* __restrict__ logits,   // [B,Q,C]
                           const float* __restrict__ pboxes,   // [B,Q,4]
                           const int*   __restrict__ tids,     // [B,T]
                           const float* __restrict__ tboxes,   // [B,T,4]
                           const float* __restrict__ imgsz,    // [B,4]
                           float*       __restrict__ out)
{
    extern __shared__ float sm[];
    float* Cm     = sm;                    // QQ*TPAD
    float* bn     = Cm + QQ * TPAD;        // QQ*4 normalized pred boxes
    float* praw   = bn + QQ * 4;           // QQ*4 raw pred boxes
    float* pa     = praw + QQ * 4;         // QQ pred areas
    float* tn     = pa + QQ;               // TT*4 normalized tgt boxes
    float* traw   = tn + TT * 4;           // TT*4 raw tgt boxes
    float* ta     = traw + TT * 4;         // TT tgt areas
    float* rowmin = ta + TT;               // QQ
    int*   rowarg = (int*)(rowmin + QQ);   // QQ
    int*   cls    = rowarg + QQ;           // TT
    int*   colused= cls + TT;              // TT

    __shared__ unsigned long long red;
    __shared__ int cur_j;

    const int b   = blockIdx.x;
    const int tid = threadIdx.x;

    float ix, iy, iz, iw;
    {
        const float* is = imgsz + b * 4;
        ix = 1.0f / is[0]; iy = 1.0f / is[1];
        iz = 1.0f / is[2]; iw = 1.0f / is[3];
    }

    if (tid < TT) {
        cls[tid] = tids[b * TT + tid];
        float4 tb = ((const float4*)tboxes)[b * TT + tid];
        traw[tid * 4 + 0] = tb.x; traw[tid * 4 + 1] = tb.y;
        traw[tid * 4 + 2] = tb.z; traw[tid * 4 + 3] = tb.w;
        tn[tid * 4 + 0] = tb.x * ix; tn[tid * 4 + 1] = tb.y * iy;
        tn[tid * 4 + 2] = tb.z * iz; tn[tid * 4 + 3] = tb.w * iw;
        ta[tid] = (tb.z - tb.x) * (tb.w - tb.y);
        colused[tid] = 0;
    }
    for (int q = tid; q < QQ; q += NTHREADS) {
        float4 pb = ((const float4*)pboxes)[b * QQ + q];
        praw[q * 4 + 0] = pb.x; praw[q * 4 + 1] = pb.y;
        praw[q * 4 + 2] = pb.z; praw[q * 4 + 3] = pb.w;
        bn[q * 4 + 0] = pb.x * ix; bn[q * 4 + 1] = pb.y * iy;
        bn[q * 4 + 2] = pb.z * iz; bn[q * 4 + 3] = pb.w * iw;
        pa[q] = (pb.z - pb.x) * (pb.w - pb.y);
    }
    __syncthreads();

    // ---- Phase 1: cost matrix (smem + gmem) ----
    const float* lg   = logits + (size_t)b * QQ * NCLS;
    float*       Cout = out    + (size_t)b * QQ * TT;

    for (int idx = tid; idx < QQ * TT; idx += NTHREADS) {
        int q = idx >> 6;
        int t = idx & 63;

        // focal class cost for the target class
        float x = lg[q * NCLS + cls[t]];
        float p = 1.0f / (1.0f + expf(-x));
        float omp = 1.0f - p;
        float pos = 0.25f * omp * omp * (-logf(p + 1e-8f));
        float neg = 0.75f * p * p * (-log1pf(-p + 1e-8f));
        float ccost = pos - neg;

        // L1 on normalized boxes
        float l1 = fabsf(bn[q * 4 + 0] - tn[t * 4 + 0])
                 + fabsf(bn[q * 4 + 1] - tn[t * 4 + 1])
                 + fabsf(bn[q * 4 + 2] - tn[t * 4 + 2])
                 + fabsf(bn[q * 4 + 3] - tn[t * 4 + 3]);

        // GIoU on raw boxes
        float ax1 = praw[q * 4 + 0], ay1 = praw[q * 4 + 1];
        float ax2 = praw[q * 4 + 2], ay2 = praw[q * 4 + 3];
        float bx1 = traw[t * 4 + 0], by1 = traw[t * 4 + 1];
        float bx2 = traw[t * 4 + 2], by2 = traw[t * 4 + 3];

        float iwd = fmaxf(fminf(ax2, bx2) - fmaxf(ax1, bx1), 0.0f);
        float ihd = fmaxf(fminf(ay2, by2) - fmaxf(ay1, by1), 0.0f);
        float inter = iwd * ihd;
        float uni = pa[q] + ta[t] - inter;
        float iou = inter / uni;
        float ewd = fmaxf(fmaxf(ax2, bx2) - fminf(ax1, bx1), 0.0f);
        float ehd = fmaxf(fmaxf(ay2, by2) - fminf(ay1, by1), 0.0f);
        float enc = ewd * ehd;
        float giou = iou - (enc - uni) / enc;

        float cost = 5.0f * l1 + 2.0f * ccost - 2.0f * giou;
        Cm[q * TPAD + t] = cost;
        Cout[idx] = cost;   // coalesced
    }
    __syncthreads();

    // ---- initial row minima (first-occurrence tie-break via strict <) ----
    for (int q = tid; q < QQ; q += NTHREADS) {
        float best = INFINITY; int ba = 0;
        const float* row = Cm + q * TPAD;
        #pragma unroll 8
        for (int j = 0; j < TT; j++) {
            float v = row[j];
            if (v < best) { best = v; ba = j; }
        }
        rowmin[q] = best; rowarg[q] = ba;
    }
    __syncthreads();

    float* rows_out = out + (size_t)BB * QQ * TT;
    float* cols_out = rows_out + (size_t)BB * TT;

    // ---- Phase 2: greedy assignment, 64 dependent steps ----
    for (int t = 0; t < TT; t++) {
        if (tid == 0) red = 0xFFFFFFFFFFFFFFFFull;
        __syncthreads();

        unsigned long long key = 0xFFFFFFFFFFFFFFFFull;
        if (tid < QQ) {
            key = ((unsigned long long)f2ord(rowmin[tid]) << 32) | (unsigned int)tid;
        }
        #pragma unroll
        for (int off = 16; off; off >>= 1) {
            unsigned long long o = __shfl_down_sync(0xffffffffu, key, off);
            key = (o < key) ? o : key;
        }
        if ((tid & 31) == 0) atomicMin(&red, key);
        __syncthreads();

        if (tid == 0) {
            int i = (int)(red & 0xFFFFFFFFu);
            int j = rowarg[i];
            cur_j = j;
            colused[j] = 1;
            rowmin[i] = INFINITY;
            rows_out[b * TT + t] = (float)i;
            cols_out[b * TT + t] = (float)j;
        }
        __syncthreads();

        if (t < TT - 1) {
            int j = cur_j;
            // only rows whose cached argmin column was consumed rescan
            for (int q = tid; q < QQ; q += NTHREADS) {
                if (rowarg[q] == j && rowmin[q] < INFINITY) {
                    float best = INFINITY; int ba = 0;
                    const float* row = Cm + q * TPAD;
                    for (int jj = 0; jj < TT; jj++) {
                        if (!colused[jj]) {
                            float v = row[jj];
                            if (v < best) { best = v; ba = jj; }
                        }
                    }
                    rowmin[q] = best; rowarg[q] = ba;
                }
            }
            __syncthreads();
        }
    }
}

extern "C" void kernel_launch(void* const* d_in, const int* in_sizes, int n_in,
                              void* d_out, int out_size) {
    const float* logits = (const float*)d_in[0];   // [128,500,80]
    const float* pboxes = (const float*)d_in[1];   // [128,500,4]
    const int*   tids   = (const int*)  d_in[2];   // [128,64]
    const float* tboxes = (const float*)d_in[3];   // [128,64,4]
    const float* imgsz  = (const float*)d_in[4];   // [128,4]
    float* out = (float*)d_out;

    const int smem_bytes =
        (QQ * TPAD + QQ * 4 + QQ * 4 + QQ + TT * 4 + TT * 4 + TT + QQ) * (int)sizeof(float)
        + (QQ + TT + TT) * (int)sizeof(int);

    cudaFuncSetAttribute(hungarian_lite_kernel,
                         cudaFuncAttributeMaxDynamicSharedMemorySize, smem_bytes);
    hungarian_lite_kernel<<<BB, NTHREADS, smem_bytes>>>(logits, pboxes, tids,
                                                        tboxes, imgsz, out);
}